// round 5
// baseline (speedup 1.0000x reference)
#include <cuda_runtime.h>
#include <cuda_bf16.h>
#include <math.h>
#include <stdint.h>

#define FULLMASK 0xffffffffu
#define NCLS 10
#define MAXM 131072
#define MAXN 2048
#define NSPLIT 9

// quantization: Q = round(v * 4096), 16-bit, split into bytes a1,a0
#define QSCALE 4096.0f

// ---------------- scratch (static device globals; no allocation) ------------
__device__ int8_t g_zc_q1[MAXM * 128];
__device__ int8_t g_zc_q0[MAXM * 128];
__device__ float  g_cn[MAXM];
__device__ int8_t g_z_q1[MAXN * 128];
__device__ int8_t g_z_q0[MAXN * 128];
__device__ float  g_zn2[MAXN];
__device__ int    g_destMap[MAXM];
__device__ int    g_hist[(MAXM / 32) * NCLS];
__device__ int    g_classStart[NCLS + 1];
__device__ float  g_part[NSPLIT * MAXN * NCLS];

// ---------------- PTX helpers (baseline sm_80+ only) -------------------------
__device__ __forceinline__ uint32_t smem_u32(const void* p) {
    uint32_t a;
    asm("{ .reg .u64 t; cvta.to.shared.u64 t, %1; cvt.u32.u64 %0, t; }" : "=r"(a) : "l"(p));
    return a;
}

#define CP16(saddr, gptr) \
    asm volatile("cp.async.cg.shared.global [%0], [%1], 16;" :: "r"(saddr), "l"(gptr))
#define CP_COMMIT() asm volatile("cp.async.commit_group;" ::: "memory")
#define CP_WAIT(n)  asm volatile("cp.async.wait_group %0;" :: "n"(n) : "memory")

#define LDSM4(r, addr) \
    asm volatile("ldmatrix.sync.aligned.m8n8.x4.shared.b16 {%0,%1,%2,%3}, [%4];" \
        : "=r"((r)[0]), "=r"((r)[1]), "=r"((r)[2]), "=r"((r)[3]) : "r"(addr))

#define MMA_S8(d, a, b0v, b1v) \
    asm volatile("mma.sync.aligned.m16n8k32.row.col.s32.s8.s8.s32 " \
        "{%0,%1,%2,%3},{%4,%5,%6,%7},{%8,%9},{%0,%1,%2,%3};" \
        : "+r"((d)[0]), "+r"((d)[1]), "+r"((d)[2]), "+r"((d)[3]) \
        : "r"((a)[0]), "r"((a)[1]), "r"((a)[2]), "r"((a)[3]), "r"(b0v), "r"(b1v))

// ---------------- counting sort by class (deterministic, stable) ------------
__global__ void hist_k(const int* __restrict__ y, int M, int* __restrict__ hist) {
    int i = blockIdx.x * 32 + threadIdx.x;
    int c = (i < M) ? y[i] : -1;
#pragma unroll
    for (int cls = 0; cls < NCLS; ++cls) {
        unsigned b = __ballot_sync(FULLMASK, c == cls);
        if (threadIdx.x == 0) hist[blockIdx.x * NCLS + cls] = __popc(b);
    }
}

__global__ void scan_k(int* hist, int NB, int* classStart) {
    __shared__ int tot[NCLS];
    int c = threadIdx.x;
    if (c < NCLS) {
        int run = 0;
        for (int b = 0; b < NB; ++b) {
            int t = hist[b * NCLS + c];
            hist[b * NCLS + c] = run;
            run += t;
        }
        tot[c] = run;
    }
    __syncthreads();
    if (threadIdx.x == 0) {
        int a = 0;
        for (int i = 0; i < NCLS; ++i) { classStart[i] = a; a += tot[i]; }
        classStart[NCLS] = a;
    }
}

__global__ void scatter_k(const int* __restrict__ y, int M,
                          const int* __restrict__ hist,
                          const int* __restrict__ classStart,
                          int* __restrict__ dest) {
    int lane = threadIdx.x;
    int i = blockIdx.x * 32 + lane;
    int c = (i < M) ? y[i] : -1;
    unsigned mymask = 0;
#pragma unroll
    for (int cls = 0; cls < NCLS; ++cls) {
        unsigned b = __ballot_sync(FULLMASK, c == cls);
        if (c == cls) mymask = b;
    }
    if (i < M) {
        int rank = __popc(mymask & ((1u << lane) - 1u));
        dest[i] = classStart[c] + hist[blockIdx.x * NCLS + c] + rank;
    }
}

// ---------------- encoder: out[dest] = X[src]@W^T + b -> int8 pair + norms ---
__global__ __launch_bounds__(256, 2)
void encode_k(const float* __restrict__ X, int n, const int* __restrict__ destMap,
              const float* __restrict__ W, const float* __restrict__ bias,
              int8_t* __restrict__ outQ1, int8_t* __restrict__ outQ0,
              float* __restrict__ outN) {
    extern __shared__ char smc[];
    float* sm = (float*)smc;
    float* ws = sm;                       // [128][132]
    float* xs = sm + 128 * 132;           // [32][132]
    int*   dests = (int*)(sm + 128 * 132 + 32 * 132);

    int tid = threadIdx.x;
    int base = blockIdx.x * 32;

    for (int t = tid; t < 128 * 32; t += 256) {
        int row = t >> 5, q = t & 31;
        float4 v = ((const float4*)W)[row * 32 + q];
        *(float4*)&ws[row * 132 + q * 4] = v;
    }
    for (int t = tid; t < 32 * 32; t += 256) {
        int row = t >> 5, q = t & 31;
        float4 v = make_float4(0.f, 0.f, 0.f, 0.f);
        if (base + row < n) v = ((const float4*)X)[(size_t)(base + row) * 32 + q];
        *(float4*)&xs[row * 132 + q * 4] = v;
    }
    if (tid < 32)
        dests[tid] = (base + tid < n) ? (destMap ? destMap[base + tid] : base + tid) : -1;
    __syncthreads();

    int cgrp = tid & 31, rgrp = tid >> 5;
    float acc[4][4];
#pragma unroll
    for (int i = 0; i < 4; ++i)
#pragma unroll
        for (int j = 0; j < 4; ++j) acc[i][j] = 0.f;

#pragma unroll 4
    for (int k = 0; k < 128; k += 4) {
        float4 a[4], w4[4];
#pragma unroll
        for (int i = 0; i < 4; ++i) a[i] = *(const float4*)&xs[(rgrp * 4 + i) * 132 + k];
#pragma unroll
        for (int j = 0; j < 4; ++j) w4[j] = *(const float4*)&ws[(cgrp + 32 * j) * 132 + k];
#pragma unroll
        for (int i = 0; i < 4; ++i)
#pragma unroll
            for (int j = 0; j < 4; ++j) {
                acc[i][j] = fmaf(a[i].x, w4[j].x, acc[i][j]);
                acc[i][j] = fmaf(a[i].y, w4[j].y, acc[i][j]);
                acc[i][j] = fmaf(a[i].z, w4[j].z, acc[i][j]);
                acc[i][j] = fmaf(a[i].w, w4[j].w, acc[i][j]);
            }
    }

    float nrm[4] = {0.f, 0.f, 0.f, 0.f};
#pragma unroll
    for (int j = 0; j < 4; ++j) {
        int dim = cgrp + 32 * j;
        float bb = bias[dim];
#pragma unroll
        for (int i = 0; i < 4; ++i) {
            float v = acc[i][j] + bb;
            acc[i][j] = v;
            nrm[i] = fmaf(v, v, nrm[i]);
        }
    }
#pragma unroll
    for (int i = 0; i < 4; ++i) {
        int d = dests[rgrp * 4 + i];
        if (d >= 0) {
#pragma unroll
            for (int j = 0; j < 4; ++j) {
                float v = acc[i][j];
                int Q = __float2int_rn(v * QSCALE);
                Q = max(-32640, min(32639, Q));
                int a1 = (Q + 128) >> 8;
                int a0 = Q - (a1 << 8);
                outQ1[(size_t)d * 128 + cgrp + 32 * j] = (int8_t)a1;
                outQ0[(size_t)d * 128 + cgrp + 32 * j] = (int8_t)a0;
            }
        }
        float s = nrm[i];
#pragma unroll
        for (int off = 16; off > 0; off >>= 1) s += __shfl_xor_sync(FULLMASK, s, off);
        if (cgrp == 0 && d >= 0) outN[d] = s;
    }
}

// ---------------- main: IMMA s8 16-bit-split dist + per-class numerators -----
// smem layout (bytes). int8 tiles: 128 rows x 128B, XOR-8 16B-chunk swizzle.
#define SM_ZQ1   0
#define SM_ZQ0   16384
#define SM_B     32768     // 3 stages x 32768 (q1 at +0, q0 at +16384)
#define SM_CN    131072    // 3 x 512
#define SM_SACC  132608    // 128*10 floats = 5120
#define SM_TOTAL 137728

// async-copy one 128x128 int8 tile (16KB) into swizzled smem; 512 threads
__device__ __forceinline__ void issue_tile(uint32_t sbase, const uint4* __restrict__ g,
                                           int tid) {
#pragma unroll
    for (int t = 0; t < 2; ++t) {
        int idx = tid + t * 512;            // 0..1023, = row*8 + chunk
        int row = idx >> 3, c = idx & 7;
        uint32_t saddr = sbase + row * 128 + ((c ^ (row & 7)) << 4);
        CP16(saddr, g + idx);
    }
}

__global__ __launch_bounds__(512, 1)
void nca_mma_k(const int8_t* __restrict__ zq1_g, const int8_t* __restrict__ zq0_g,
               const float* __restrict__ zn2,
               const int8_t* __restrict__ cq1_g, const int8_t* __restrict__ cq0_g,
               const float* __restrict__ cn_g, const int* __restrict__ classStart,
               float* __restrict__ part, int M, int N) {
    extern __shared__ char smc[];
    char* sm = smc;
    const uint32_t sb = smem_u32(sm);
    const int tid = threadIdx.x;
    const int w = tid >> 5, lane = tid & 31;
    const int warpM = w & 3, warpN = w >> 2;   // 4 x 4 warp grid; 32 x 32 per warp
    const int q2 = (lane & 3) * 2;
    const int tile = blockIdx.x, split = blockIdx.y;
    const int chunksTotal = M >> 7;
    const int cpb = (chunksTotal + NSPLIT - 1) / NSPLIT;
    const int cLo = split * cpb;
    const int cHi = min(cLo + cpb, chunksTotal);
    const int nch = cHi - cLo;

    for (int i = tid; i < 128 * NCLS; i += 512) ((float*)(sm + SM_SACC))[i] = 0.f;

    int cs[NCLS + 1];
#pragma unroll
    for (int k = 0; k <= NCLS; ++k) cs[k] = classStart[k];

    float znr[2][2];
#pragma unroll
    for (int mi = 0; mi < 2; ++mi) {
        int r = tile * 128 + warpM * 32 + mi * 16 + (lane >> 2);
        znr[mi][0] = zn2[r];
        znr[mi][1] = zn2[r + 8];
    }

    // prologue: group0 = z tiles + stage0, group1 = stage1
    issue_tile(sb + SM_ZQ1, (const uint4*)zq1_g + (size_t)tile * 1024, tid);
    issue_tile(sb + SM_ZQ0, (const uint4*)zq0_g + (size_t)tile * 1024, tid);
    issue_tile(sb + SM_B,         (const uint4*)cq1_g + (size_t)cLo * 1024, tid);
    issue_tile(sb + SM_B + 16384, (const uint4*)cq0_g + (size_t)cLo * 1024, tid);
    if (tid < 32) CP16(sb + SM_CN + tid * 16, (const float*)cn_g + (size_t)cLo * 128 + tid * 4);
    CP_COMMIT();
    if (nch > 1) {
        issue_tile(sb + SM_B + 32768,         (const uint4*)cq1_g + (size_t)(cLo + 1) * 1024, tid);
        issue_tile(sb + SM_B + 32768 + 16384, (const uint4*)cq0_g + (size_t)(cLo + 1) * 1024, tid);
        if (tid < 32) CP16(sb + SM_CN + 512 + tid * 16,
                           (const float*)cn_g + (size_t)(cLo + 1) * 128 + tid * 4);
    }
    CP_COMMIT();

    // ldmatrix row/addr precompute
    uint32_t arow[2];
#pragma unroll
    for (int mi = 0; mi < 2; ++mi) arow[mi] = warpM * 32 + mi * 16 + (lane & 15);
    const uint32_t achb = lane >> 4;            // chunk-half bit for A
    uint32_t brow[2];
#pragma unroll
    for (int g = 0; g < 2; ++g)
        brow[g] = warpN * 32 + g * 16 + (lane & 7) + ((lane >> 4) << 3);
    const uint32_t bchb = (lane >> 3) & 1;

    for (int i = 0; i < nch; ++i) {
        CP_WAIT(1);
        __syncthreads();

        const int st = i % 3;
        const uint32_t bq1 = sb + SM_B + st * 32768;
        const uint32_t zq1 = sb + SM_ZQ1;

        int accA[2][4][4], accM[2][4][4];
#pragma unroll
        for (int mi = 0; mi < 2; ++mi)
#pragma unroll
            for (int ni = 0; ni < 4; ++ni)
#pragma unroll
                for (int k = 0; k < 4; ++k) { accA[mi][ni][k] = 0; accM[mi][ni][k] = 0; }

#pragma unroll
        for (int ks = 0; ks < 4; ++ks) {
            uint32_t a1f[2][4], a0f[2][4], b1f[2][4], b0f[2][4];
            uint32_t ca = 2 * ks + achb, cb = 2 * ks + bchb;
#pragma unroll
            for (int mi = 0; mi < 2; ++mi) {
                uint32_t ad = zq1 + arow[mi] * 128 + ((ca ^ (arow[mi] & 7)) << 4);
                LDSM4(a1f[mi], ad);
                LDSM4(a0f[mi], ad + 16384);
            }
#pragma unroll
            for (int g = 0; g < 2; ++g) {
                uint32_t bd = bq1 + brow[g] * 128 + ((cb ^ (brow[g] & 7)) << 4);
                LDSM4(b1f[g], bd);
                LDSM4(b0f[g], bd + 16384);
            }
#pragma unroll
            for (int mi = 0; mi < 2; ++mi)
#pragma unroll
                for (int ni = 0; ni < 4; ++ni) {
                    int g = ni >> 1, p = (ni & 1) * 2;
                    MMA_S8(accA[mi][ni], a1f[mi], b1f[g][p], b1f[g][p + 1]);
                    MMA_S8(accM[mi][ni], a1f[mi], b0f[g][p], b0f[g][p + 1]);
                    MMA_S8(accM[mi][ni], a0f[mi], b1f[g][p], b1f[g][p + 1]);
                }
        }

        // epilogue: dot = 2^-8*accA + 2^-16*accM; sq = zn+cn-2*dot
        float fe[2][4][4];
#pragma unroll
        for (int ni = 0; ni < 4; ++ni) {
            float cn0 = *(const float*)(sm + SM_CN + st * 512 + (warpN * 32 + ni * 8 + q2) * 4);
            float cn1 = *(const float*)(sm + SM_CN + st * 512 + (warpN * 32 + ni * 8 + q2 + 1) * 4);
#pragma unroll
            for (int mi = 0; mi < 2; ++mi)
#pragma unroll
                for (int k = 0; k < 4; ++k) {
                    float base = znr[mi][k >> 1] + ((k & 1) ? cn1 : cn0);
                    float sq = fmaf(-0.0078125f, (float)accA[mi][ni][k],
                              fmaf(-0.000030517578125f, (float)accM[mi][ni][k], base));
                    sq = fmaxf(sq, 1e-12f);
                    float dd;
                    asm("sqrt.approx.f32 %0, %1;" : "=f"(dd) : "f"(sq));
                    asm("ex2.approx.f32 %0, %1;" : "=f"(fe[mi][ni][k])
                        : "f"(dd * -1.4426950408889634f));
                }
        }

        // class-segmented accumulation (candidates sorted by class)
        const int wb = (cLo + i) * 128 + warpN * 32;
        int c0 = 0;
        while (c0 < NCLS - 1 && cs[c0 + 1] <= wb) ++c0;
        int c1 = c0;
        while (c1 < NCLS - 1 && cs[c1 + 1] < wb + 32) ++c1;
        for (int c = c0; c <= c1; ++c) {
            int lo = max(cs[c] - wb, 0), hi = min(cs[c + 1] - wb, 32);
#pragma unroll
            for (int mi = 0; mi < 2; ++mi)
#pragma unroll
                for (int h = 0; h < 2; ++h) {
                    float s = 0.f;
#pragma unroll
                    for (int ni = 0; ni < 4; ++ni)
#pragma unroll
                        for (int j = 0; j < 2; ++j) {
                            int nl = ni * 8 + q2 + j;
                            s += (nl >= lo && nl < hi) ? fe[mi][ni][h * 2 + j] : 0.f;
                        }
                    s += __shfl_xor_sync(FULLMASK, s, 1);
                    s += __shfl_xor_sync(FULLMASK, s, 2);
                    if ((lane & 3) == 0) {
                        int r = warpM * 32 + mi * 16 + (lane >> 2) + h * 8;
                        atomicAdd((float*)(sm + SM_SACC) + r * NCLS + c, s);
                    }
                }
        }

        // prefetch stage i+2 (buffer freed by this iteration's barrier)
        if (i + 2 < nch) {
            int ns = (i + 2) % 3;
            issue_tile(sb + SM_B + ns * 32768,
                       (const uint4*)cq1_g + (size_t)(cLo + i + 2) * 1024, tid);
            issue_tile(sb + SM_B + ns * 32768 + 16384,
                       (const uint4*)cq0_g + (size_t)(cLo + i + 2) * 1024, tid);
            if (tid < 32) CP16(sb + SM_CN + ns * 512 + tid * 16,
                               (const float*)cn_g + (size_t)(cLo + i + 2) * 128 + tid * 4);
        }
        CP_COMMIT();
    }

    __syncthreads();
    if (tid < 128) {
        int qg = tile * 128 + tid;
#pragma unroll
        for (int c = 0; c < NCLS; ++c)
            part[((size_t)split * N + qg) * NCLS + c] =
                ((float*)(sm + SM_SACC))[tid * NCLS + c];
    }
}

// ---------------- finalize: combine splits, normalize, log ------------------
__global__ void finalize_k(const float* __restrict__ part, float* __restrict__ out, int N) {
    int n = blockIdx.x * blockDim.x + threadIdx.x;
    if (n >= N) return;
    float t[NCLS];
#pragma unroll
    for (int c = 0; c < NCLS; ++c) t[c] = 0.f;
    for (int s = 0; s < NSPLIT; ++s)
#pragma unroll
        for (int c = 0; c < NCLS; ++c) t[c] += part[((size_t)s * N + n) * NCLS + c];
    float tot = 0.f;
#pragma unroll
    for (int c = 0; c < NCLS; ++c) tot += t[c];
    float inv = 1.f / tot;
#pragma unroll
    for (int c = 0; c < NCLS; ++c) out[n * NCLS + c] = logf(fmaf(t[c], inv, 1e-7f));
}

// ---------------- launch ----------------------------------------------------
extern "C" void kernel_launch(void* const* d_in, const int* in_sizes, int n_in,
                              void* d_out, int out_size) {
    const float* x  = (const float*)d_in[0];
    const float* cx = (const float*)d_in[1];
    const int*   cy = (const int*)d_in[2];
    const float* W  = (const float*)d_in[3];
    const float* b  = (const float*)d_in[4];
    int N = in_sizes[0] / 128;
    int M = in_sizes[2];
    float* out = (float*)d_out;

    void *p_cq1, *p_cq0, *p_cn, *p_zq1, *p_zq0, *p_zn2, *p_dest, *p_hist, *p_cs, *p_part;
    cudaGetSymbolAddress(&p_cq1, g_zc_q1);
    cudaGetSymbolAddress(&p_cq0, g_zc_q0);
    cudaGetSymbolAddress(&p_cn, g_cn);
    cudaGetSymbolAddress(&p_zq1, g_z_q1);
    cudaGetSymbolAddress(&p_zq0, g_z_q0);
    cudaGetSymbolAddress(&p_zn2, g_zn2);
    cudaGetSymbolAddress(&p_dest, g_destMap);
    cudaGetSymbolAddress(&p_hist, g_hist);
    cudaGetSymbolAddress(&p_cs, g_classStart);
    cudaGetSymbolAddress(&p_part, g_part);

    int NB = (M + 31) / 32;
    hist_k<<<NB, 32>>>(cy, M, (int*)p_hist);
    scan_k<<<1, 32>>>((int*)p_hist, NB, (int*)p_cs);
    scatter_k<<<NB, 32>>>(cy, M, (const int*)p_hist, (const int*)p_cs, (int*)p_dest);

    size_t smemEnc = (size_t)(128 * 132 + 32 * 132) * 4 + 32 * 4;
    cudaFuncSetAttribute(encode_k, cudaFuncAttributeMaxDynamicSharedMemorySize, (int)smemEnc);
    encode_k<<<(N + 31) / 32, 256, smemEnc>>>(x, N, nullptr, W, b,
        (int8_t*)p_zq1, (int8_t*)p_zq0, (float*)p_zn2);
    encode_k<<<(M + 31) / 32, 256, smemEnc>>>(cx, M, (const int*)p_dest, W, b,
        (int8_t*)p_cq1, (int8_t*)p_cq0, (float*)p_cn);

    cudaFuncSetAttribute(nca_mma_k, cudaFuncAttributeMaxDynamicSharedMemorySize, SM_TOTAL);
    dim3 g(N / 128, NSPLIT);
    nca_mma_k<<<g, 512, SM_TOTAL>>>(
        (const int8_t*)p_zq1, (const int8_t*)p_zq0, (const float*)p_zn2,
        (const int8_t*)p_cq1, (const int8_t*)p_cq0, (const float*)p_cn,
        (const int*)p_cs, (float*)p_part, M, N);

    finalize_k<<<(N + 255) / 256, 256>>>((const float*)p_part, out, N);
}

// round 6
// speedup vs baseline: 3.1769x; 3.1769x over previous
#include <cuda_runtime.h>
#include <cuda_fp16.h>
#include <math.h>
#include <stdint.h>

#define FULLMASK 0xffffffffu
#define NCLS 10
#define MAXM 131072
#define MAXN 2048
#define NSPLIT 18

// ---------------- scratch (static device globals; no allocation) ------------
__device__ __half g_zc_h[MAXM * 128];
__device__ float  g_cn[MAXM];
__device__ __half g_z_h[MAXN * 128];
__device__ float  g_zn2[MAXN];
__device__ int    g_destMap[MAXM];
__device__ int    g_hist[(MAXM / 32) * NCLS];
__device__ int    g_classStart[NCLS + 1];
__device__ float  g_part[NSPLIT * MAXN * NCLS];

// ---------------- PTX helpers (baseline sm_80+ only) -------------------------
__device__ __forceinline__ uint32_t smem_u32(const void* p) {
    uint32_t a;
    asm("{ .reg .u64 t; cvta.to.shared.u64 t, %1; cvt.u32.u64 %0, t; }" : "=r"(a) : "l"(p));
    return a;
}

#define CP16(saddr, gptr) \
    asm volatile("cp.async.cg.shared.global [%0], [%1], 16;" :: "r"(saddr), "l"(gptr))
#define CP_COMMIT() asm volatile("cp.async.commit_group;" ::: "memory")
#define CP_WAIT(n)  asm volatile("cp.async.wait_group %0;" :: "n"(n) : "memory")

#define LDSM4(r, addr) \
    asm volatile("ldmatrix.sync.aligned.m8n8.x4.shared.b16 {%0,%1,%2,%3}, [%4];" \
        : "=r"((r)[0]), "=r"((r)[1]), "=r"((r)[2]), "=r"((r)[3]) : "r"(addr))

#define MMA_F16(d, a, b0v, b1v) \
    asm volatile("mma.sync.aligned.m16n8k16.row.col.f32.f16.f16.f32 " \
        "{%0,%1,%2,%3},{%4,%5,%6,%7},{%8,%9},{%0,%1,%2,%3};" \
        : "+f"((d)[0]), "+f"((d)[1]), "+f"((d)[2]), "+f"((d)[3]) \
        : "r"((a)[0]), "r"((a)[1]), "r"((a)[2]), "r"((a)[3]), "r"(b0v), "r"(b1v))

// ---------------- counting sort by class (deterministic, stable) ------------
__global__ void hist_k(const int* __restrict__ y, int M, int* __restrict__ hist) {
    int i = blockIdx.x * 32 + threadIdx.x;
    int c = (i < M) ? y[i] : -1;
#pragma unroll
    for (int cls = 0; cls < NCLS; ++cls) {
        unsigned b = __ballot_sync(FULLMASK, c == cls);
        if (threadIdx.x == 0) hist[blockIdx.x * NCLS + cls] = __popc(b);
    }
}

__global__ void scan_k(int* hist, int NB, int* classStart) {
    __shared__ int tot[NCLS];
    int c = threadIdx.x;
    if (c < NCLS) {
        int run = 0;
        for (int b = 0; b < NB; ++b) {
            int t = hist[b * NCLS + c];
            hist[b * NCLS + c] = run;
            run += t;
        }
        tot[c] = run;
    }
    __syncthreads();
    if (threadIdx.x == 0) {
        int a = 0;
        for (int i = 0; i < NCLS; ++i) { classStart[i] = a; a += tot[i]; }
        classStart[NCLS] = a;
    }
}

__global__ void scatter_k(const int* __restrict__ y, int M,
                          const int* __restrict__ hist,
                          const int* __restrict__ classStart,
                          int* __restrict__ dest) {
    int lane = threadIdx.x;
    int i = blockIdx.x * 32 + lane;
    int c = (i < M) ? y[i] : -1;
    unsigned mymask = 0;
#pragma unroll
    for (int cls = 0; cls < NCLS; ++cls) {
        unsigned b = __ballot_sync(FULLMASK, c == cls);
        if (c == cls) mymask = b;
    }
    if (i < M) {
        int rank = __popc(mymask & ((1u << lane) - 1u));
        dest[i] = classStart[c] + hist[blockIdx.x * NCLS + c] + rank;
    }
}

// ---------------- encoder: out[dest] = X[src]@W^T + b -> fp16 + norms --------
__global__ __launch_bounds__(256, 2)
void encode_k(const float* __restrict__ X, int n, const int* __restrict__ destMap,
              const float* __restrict__ W, const float* __restrict__ bias,
              __half* __restrict__ outH, float* __restrict__ outN) {
    extern __shared__ char smc[];
    float* sm = (float*)smc;
    float* ws = sm;                       // [128][132]
    float* xs = sm + 128 * 132;           // [32][132]
    int*   dests = (int*)(sm + 128 * 132 + 32 * 132);

    int tid = threadIdx.x;
    int base = blockIdx.x * 32;

    for (int t = tid; t < 128 * 32; t += 256) {
        int row = t >> 5, q = t & 31;
        float4 v = ((const float4*)W)[row * 32 + q];
        *(float4*)&ws[row * 132 + q * 4] = v;
    }
    for (int t = tid; t < 32 * 32; t += 256) {
        int row = t >> 5, q = t & 31;
        float4 v = make_float4(0.f, 0.f, 0.f, 0.f);
        if (base + row < n) v = ((const float4*)X)[(size_t)(base + row) * 32 + q];
        *(float4*)&xs[row * 132 + q * 4] = v;
    }
    if (tid < 32)
        dests[tid] = (base + tid < n) ? (destMap ? destMap[base + tid] : base + tid) : -1;
    __syncthreads();

    int cgrp = tid & 31, rgrp = tid >> 5;
    float acc[4][4];
#pragma unroll
    for (int i = 0; i < 4; ++i)
#pragma unroll
        for (int j = 0; j < 4; ++j) acc[i][j] = 0.f;

#pragma unroll 4
    for (int k = 0; k < 128; k += 4) {
        float4 a[4], w4[4];
#pragma unroll
        for (int i = 0; i < 4; ++i) a[i] = *(const float4*)&xs[(rgrp * 4 + i) * 132 + k];
#pragma unroll
        for (int j = 0; j < 4; ++j) w4[j] = *(const float4*)&ws[(cgrp + 32 * j) * 132 + k];
#pragma unroll
        for (int i = 0; i < 4; ++i)
#pragma unroll
            for (int j = 0; j < 4; ++j) {
                acc[i][j] = fmaf(a[i].x, w4[j].x, acc[i][j]);
                acc[i][j] = fmaf(a[i].y, w4[j].y, acc[i][j]);
                acc[i][j] = fmaf(a[i].z, w4[j].z, acc[i][j]);
                acc[i][j] = fmaf(a[i].w, w4[j].w, acc[i][j]);
            }
    }

    float nrm[4] = {0.f, 0.f, 0.f, 0.f};
#pragma unroll
    for (int j = 0; j < 4; ++j) {
        int dim = cgrp + 32 * j;
        float bb = bias[dim];
#pragma unroll
        for (int i = 0; i < 4; ++i) {
            float v = acc[i][j] + bb;
            acc[i][j] = v;
            nrm[i] = fmaf(v, v, nrm[i]);
        }
    }
#pragma unroll
    for (int i = 0; i < 4; ++i) {
        int d = dests[rgrp * 4 + i];
        if (d >= 0) {
#pragma unroll
            for (int j = 0; j < 4; ++j)
                outH[(size_t)d * 128 + cgrp + 32 * j] = __float2half_rn(acc[i][j]);
        }
        float s = nrm[i];
#pragma unroll
        for (int off = 16; off > 0; off >>= 1) s += __shfl_xor_sync(FULLMASK, s, off);
        if (cgrp == 0 && d >= 0) outN[d] = s;
    }
}

// ---------------- main: single-term fp16 HMMA dist + per-class numerators ----
// smem (bytes): fp16 tiles 128 rows x 256B, XOR-8 16B-chunk swizzle.
#define SM_ZH    0
#define SM_B     32768     // 2 stages x 32768
#define SM_CN    98304     // 2 x 512
#define SM_SACC  99328     // 128*10 floats
#define SM_TOTAL 104448

// async-copy one 128x128 fp16 tile (32KB) into swizzled smem; 256 threads
__device__ __forceinline__ void issue_tile(uint32_t sbase, const uint4* __restrict__ g,
                                           int tid) {
#pragma unroll
    for (int t = 0; t < 8; ++t) {
        int idx = tid + t * 256;            // 0..2047, = row*16 + chunk
        int row = idx >> 4, c = idx & 15;
        uint32_t saddr = sbase + row * 256 + ((c ^ (row & 7)) << 4);
        CP16(saddr, g + idx);
    }
}

__global__ __launch_bounds__(256, 2)
void nca_mma_k(const __half* __restrict__ zh_g, const float* __restrict__ zn2,
               const __half* __restrict__ ch_g, const float* __restrict__ cn_g,
               const int* __restrict__ classStart,
               float* __restrict__ part, int M, int N) {
    extern __shared__ char smc[];
    char* sm = smc;
    const uint32_t sb = smem_u32(sm);
    const int tid = threadIdx.x;
    const int w = tid >> 5, lane = tid & 31;
    const int warpM = w & 1, warpN = w >> 1;   // 2 x 4 warp grid; 64 x 32 per warp
    const int q2 = (lane & 3) * 2;
    const int tile = blockIdx.x, split = blockIdx.y;
    const int chunksTotal = M >> 7;
    const int cpb = (chunksTotal + NSPLIT - 1) / NSPLIT;
    const int cLo = split * cpb;
    const int cHi = min(cLo + cpb, chunksTotal);
    const int nch = cHi - cLo;

    for (int i = tid; i < 128 * NCLS; i += 256) ((float*)(sm + SM_SACC))[i] = 0.f;

    int cs[NCLS + 1];
#pragma unroll
    for (int k = 0; k <= NCLS; ++k) cs[k] = classStart[k];

    float znr[4][2];
#pragma unroll
    for (int mi = 0; mi < 4; ++mi) {
        int r = tile * 128 + warpM * 64 + mi * 16 + (lane >> 2);
        znr[mi][0] = zn2[r];
        znr[mi][1] = zn2[r + 8];
    }

    // prologue: group0 = z tile + stage0, group1 = stage1
    issue_tile(sb + SM_ZH, (const uint4*)zh_g + (size_t)tile * 2048, tid);
    issue_tile(sb + SM_B, (const uint4*)ch_g + (size_t)cLo * 2048, tid);
    if (tid < 32) CP16(sb + SM_CN + tid * 16, (const float*)cn_g + (size_t)cLo * 128 + tid * 4);
    CP_COMMIT();
    if (nch > 1) {
        issue_tile(sb + SM_B + 32768, (const uint4*)ch_g + (size_t)(cLo + 1) * 2048, tid);
        if (tid < 32) CP16(sb + SM_CN + 512 + tid * 16,
                           (const float*)cn_g + (size_t)(cLo + 1) * 128 + tid * 4);
        CP_COMMIT();
    }

    // ldmatrix address precompute
    uint32_t aoff[4], asw[4];
#pragma unroll
    for (int mi = 0; mi < 4; ++mi) {
        int row = warpM * 64 + mi * 16 + (lane & 15);
        aoff[mi] = row * 256;
        asw[mi] = row & 7;
    }
    const uint32_t achb = lane >> 4;
    uint32_t boff[2], bsw[2];
#pragma unroll
    for (int g = 0; g < 2; ++g) {
        int row = warpN * 32 + g * 16 + (lane & 7) + ((lane >> 4) << 3);
        boff[g] = row * 256;
        bsw[g] = row & 7;
    }
    const uint32_t bchb = (lane >> 3) & 1;

    for (int i = 0; i < nch; ++i) {
        if (i + 1 < nch) { CP_WAIT(1); } else { CP_WAIT(0); }
        __syncthreads();

        const int cb = i & 1;
        const uint32_t bbase = sb + SM_B + cb * 32768;
        const uint32_t abase = sb + SM_ZH;

        float acc[4][4][4];
#pragma unroll
        for (int mi = 0; mi < 4; ++mi)
#pragma unroll
            for (int ni = 0; ni < 4; ++ni)
#pragma unroll
                for (int k = 0; k < 4; ++k) acc[mi][ni][k] = 0.f;

#pragma unroll
        for (int k8 = 0; k8 < 8; ++k8) {
            uint32_t af[4][4], bf[2][4];
            uint32_t ca = 2 * k8 + achb, cbk = 2 * k8 + bchb;
#pragma unroll
            for (int mi = 0; mi < 4; ++mi)
                LDSM4(af[mi], abase + aoff[mi] + ((ca ^ asw[mi]) << 4));
#pragma unroll
            for (int g = 0; g < 2; ++g)
                LDSM4(bf[g], bbase + boff[g] + ((cbk ^ bsw[g]) << 4));
#pragma unroll
            for (int mi = 0; mi < 4; ++mi)
#pragma unroll
                for (int ni = 0; ni < 4; ++ni) {
                    int g = ni >> 1, p = (ni & 1) * 2;
                    MMA_F16(acc[mi][ni], af[mi], bf[g][p], bf[g][p + 1]);
                }
        }

        // dist -> exp(-dist)
#pragma unroll
        for (int ni = 0; ni < 4; ++ni) {
            float cn0 = *(const float*)(sm + SM_CN + cb * 512 + (warpN * 32 + ni * 8 + q2) * 4);
            float cn1 = *(const float*)(sm + SM_CN + cb * 512 + (warpN * 32 + ni * 8 + q2 + 1) * 4);
#pragma unroll
            for (int mi = 0; mi < 4; ++mi)
#pragma unroll
                for (int k = 0; k < 4; ++k) {
                    float base = znr[mi][k >> 1] + ((k & 1) ? cn1 : cn0);
                    float sq = fmaxf(fmaf(-2.f, acc[mi][ni][k], base), 1e-12f);
                    float dd;
                    asm("sqrt.approx.f32 %0, %1;" : "=f"(dd) : "f"(sq));
                    asm("ex2.approx.f32 %0, %1;" : "=f"(acc[mi][ni][k])
                        : "f"(dd * -1.4426950408889634f));
                }
        }

        // class-segmented accumulation (candidates sorted by class)
        const int wb = (cLo + i) * 128 + warpN * 32;
        int c0 = 0;
        while (c0 < NCLS - 1 && cs[c0 + 1] <= wb) ++c0;
        int c1 = c0;
        while (c1 < NCLS - 1 && cs[c1 + 1] < wb + 32) ++c1;
        for (int c = c0; c <= c1; ++c) {
            int lo = max(cs[c] - wb, 0), hi = min(cs[c + 1] - wb, 32);
#pragma unroll
            for (int mi = 0; mi < 4; ++mi)
#pragma unroll
                for (int h = 0; h < 2; ++h) {
                    float s = 0.f;
#pragma unroll
                    for (int ni = 0; ni < 4; ++ni)
#pragma unroll
                        for (int j = 0; j < 2; ++j) {
                            int nl = ni * 8 + q2 + j;
                            s += (nl >= lo && nl < hi) ? acc[mi][ni][h * 2 + j] : 0.f;
                        }
                    s += __shfl_xor_sync(FULLMASK, s, 1);
                    s += __shfl_xor_sync(FULLMASK, s, 2);
                    if ((lane & 3) == 0) {
                        int r = warpM * 64 + mi * 16 + (lane >> 2) + h * 8;
                        atomicAdd((float*)(sm + SM_SACC) + r * NCLS + c, s);
                    }
                }
        }

        __syncthreads();              // all reads of buffer cb complete
        if (i + 2 < nch) {
            issue_tile(sb + SM_B + cb * 32768,
                       (const uint4*)ch_g + (size_t)(cLo + i + 2) * 2048, tid);
            if (tid < 32) CP16(sb + SM_CN + cb * 512 + tid * 16,
                               (const float*)cn_g + (size_t)(cLo + i + 2) * 128 + tid * 4);
            CP_COMMIT();
        }
    }

    __syncthreads();
    if (tid < 128) {
        int qg = tile * 128 + tid;
#pragma unroll
        for (int c = 0; c < NCLS; ++c)
            part[((size_t)split * N + qg) * NCLS + c] =
                ((float*)(sm + SM_SACC))[tid * NCLS + c];
    }
}

// ---------------- finalize: combine splits, normalize, log ------------------
__global__ void finalize_k(const float* __restrict__ part, float* __restrict__ out, int N) {
    int n = blockIdx.x * blockDim.x + threadIdx.x;
    if (n >= N) return;
    float t[NCLS];
#pragma unroll
    for (int c = 0; c < NCLS; ++c) t[c] = 0.f;
    for (int s = 0; s < NSPLIT; ++s)
#pragma unroll
        for (int c = 0; c < NCLS; ++c) t[c] += part[((size_t)s * N + n) * NCLS + c];
    float tot = 0.f;
#pragma unroll
    for (int c = 0; c < NCLS; ++c) tot += t[c];
    float inv = 1.f / tot;
#pragma unroll
    for (int c = 0; c < NCLS; ++c) out[n * NCLS + c] = logf(fmaf(t[c], inv, 1e-7f));
}

// ---------------- launch ----------------------------------------------------
extern "C" void kernel_launch(void* const* d_in, const int* in_sizes, int n_in,
                              void* d_out, int out_size) {
    const float* x  = (const float*)d_in[0];
    const float* cx = (const float*)d_in[1];
    const int*   cy = (const int*)d_in[2];
    const float* W  = (const float*)d_in[3];
    const float* b  = (const float*)d_in[4];
    int N = in_sizes[0] / 128;
    int M = in_sizes[2];
    float* out = (float*)d_out;

    void *p_ch, *p_cn, *p_zh, *p_zn2, *p_dest, *p_hist, *p_cs, *p_part;
    cudaGetSymbolAddress(&p_ch, g_zc_h);
    cudaGetSymbolAddress(&p_cn, g_cn);
    cudaGetSymbolAddress(&p_zh, g_z_h);
    cudaGetSymbolAddress(&p_zn2, g_zn2);
    cudaGetSymbolAddress(&p_dest, g_destMap);
    cudaGetSymbolAddress(&p_hist, g_hist);
    cudaGetSymbolAddress(&p_cs, g_classStart);
    cudaGetSymbolAddress(&p_part, g_part);

    int NB = (M + 31) / 32;
    hist_k<<<NB, 32>>>(cy, M, (int*)p_hist);
    scan_k<<<1, 32>>>((int*)p_hist, NB, (int*)p_cs);
    scatter_k<<<NB, 32>>>(cy, M, (const int*)p_hist, (const int*)p_cs, (int*)p_dest);

    size_t smemEnc = (size_t)(128 * 132 + 32 * 132) * 4 + 32 * 4;
    cudaFuncSetAttribute(encode_k, cudaFuncAttributeMaxDynamicSharedMemorySize, (int)smemEnc);
    encode_k<<<(N + 31) / 32, 256, smemEnc>>>(x, N, nullptr, W, b,
        (__half*)p_zh, (float*)p_zn2);
    encode_k<<<(M + 31) / 32, 256, smemEnc>>>(cx, M, (const int*)p_dest, W, b,
        (__half*)p_ch, (float*)p_cn);

    cudaFuncSetAttribute(nca_mma_k, cudaFuncAttributeMaxDynamicSharedMemorySize, SM_TOTAL);
    dim3 g(N / 128, NSPLIT);
    nca_mma_k<<<g, 256, SM_TOTAL>>>(
        (const __half*)p_zh, (const float*)p_zn2,
        (const __half*)p_ch, (const float*)p_cn,
        (const int*)p_cs, (float*)p_part, M, N);

    finalize_k<<<(N + 255) / 256, 256>>>((const float*)p_part, out, N);
}

// round 7
// speedup vs baseline: 3.8194x; 1.2022x over previous
#include <cuda_runtime.h>
#include <cuda_fp16.h>
#include <math.h>
#include <stdint.h>

#define FULLMASK 0xffffffffu
#define NCLS 10
#define MAXM 131072
#define MAXN 2048
#define NSPLIT 18
#define HB 256                 // hist/scatter block size

// scale: store z * log2(e) so ex2(-sqrt(sq')) = exp(-dist); norms * log2(e)^2
#define ZSCL 1.4426950408889634f
#define NSCL 2.081368981144074f

// ---------------- scratch (static device globals; no allocation) ------------
__device__ __half g_zc_h[MAXM * 128];
__device__ float  g_cn[MAXM];
__device__ __half g_z_h[MAXN * 128];
__device__ float  g_zn2[MAXN];
__device__ int    g_destMap[MAXM];
__device__ int    g_hist[(MAXM / HB) * NCLS];
__device__ int    g_classStart[NCLS + 1];
__device__ float  g_part[NSPLIT * MAXN * NCLS];

// ---------------- PTX helpers (baseline sm_80+ only) -------------------------
__device__ __forceinline__ uint32_t smem_u32(const void* p) {
    uint32_t a;
    asm("{ .reg .u64 t; cvta.to.shared.u64 t, %1; cvt.u32.u64 %0, t; }" : "=r"(a) : "l"(p));
    return a;
}

#define CP16(saddr, gptr) \
    asm volatile("cp.async.cg.shared.global [%0], [%1], 16;" :: "r"(saddr), "l"(gptr))
#define CP_COMMIT() asm volatile("cp.async.commit_group;" ::: "memory")
#define CP_WAIT(n)  asm volatile("cp.async.wait_group %0;" :: "n"(n) : "memory")

#define LDSM4(r, addr) \
    asm volatile("ldmatrix.sync.aligned.m8n8.x4.shared.b16 {%0,%1,%2,%3}, [%4];" \
        : "=r"((r)[0]), "=r"((r)[1]), "=r"((r)[2]), "=r"((r)[3]) : "r"(addr))

#define MMA_F16(d, a, b0v, b1v) \
    asm volatile("mma.sync.aligned.m16n8k16.row.col.f32.f16.f16.f32 " \
        "{%0,%1,%2,%3},{%4,%5,%6,%7},{%8,%9},{%0,%1,%2,%3};" \
        : "+f"((d)[0]), "+f"((d)[1]), "+f"((d)[2]), "+f"((d)[3]) \
        : "r"((a)[0]), "r"((a)[1]), "r"((a)[2]), "r"((a)[3]), "r"(b0v), "r"(b1v))

// ---------------- counting sort by class (256-thread blocks) -----------------
__global__ __launch_bounds__(HB)
void hist_k(const int* __restrict__ y, int M, int* __restrict__ hist) {
    __shared__ int wc[HB / 32][NCLS];
    int tid = threadIdx.x, w = tid >> 5;
    int i = blockIdx.x * HB + tid;
    int c = (i < M) ? y[i] : -1;
#pragma unroll
    for (int cls = 0; cls < NCLS; ++cls) {
        unsigned b = __ballot_sync(FULLMASK, c == cls);
        if ((tid & 31) == 0) wc[w][cls] = __popc(b);
    }
    __syncthreads();
    if (tid < NCLS) {
        int s = 0;
#pragma unroll
        for (int ww = 0; ww < HB / 32; ++ww) s += wc[ww][tid];
        hist[blockIdx.x * NCLS + tid] = s;
    }
}

__global__ void scan_k(int* hist, int NB, int* classStart) {
    __shared__ int tot[NCLS];
    int c = threadIdx.x;
    if (c < NCLS) {
        int run = 0;
        for (int b = 0; b < NB; ++b) {
            int t = hist[b * NCLS + c];
            hist[b * NCLS + c] = run;
            run += t;
        }
        tot[c] = run;
    }
    __syncthreads();
    if (threadIdx.x == 0) {
        int a = 0;
        for (int i = 0; i < NCLS; ++i) { classStart[i] = a; a += tot[i]; }
        classStart[NCLS] = a;
    }
}

__global__ __launch_bounds__(HB)
void scatter_k(const int* __restrict__ y, int M,
               const int* __restrict__ hist,
               const int* __restrict__ classStart,
               int* __restrict__ dest) {
    __shared__ int wc[HB / 32][NCLS];
    int tid = threadIdx.x, w = tid >> 5, lane = tid & 31;
    int i = blockIdx.x * HB + tid;
    int c = (i < M) ? y[i] : -1;
    unsigned mymask = 0;
#pragma unroll
    for (int cls = 0; cls < NCLS; ++cls) {
        unsigned b = __ballot_sync(FULLMASK, c == cls);
        if (lane == 0) wc[w][cls] = __popc(b);
        if (c == cls) mymask = b;
    }
    __syncthreads();
    if (tid < NCLS) {           // exclusive prefix over warps, per class
        int run = 0;
#pragma unroll
        for (int ww = 0; ww < HB / 32; ++ww) {
            int t = wc[ww][tid];
            wc[ww][tid] = run;
            run += t;
        }
    }
    __syncthreads();
    if (i < M) {
        int rank = __popc(mymask & ((1u << lane) - 1u));
        dest[i] = classStart[c] + hist[blockIdx.x * NCLS + c] + wc[w][c] + rank;
    }
}

// ---------------- encoder: out[dest] = X[src]@W^T + b -> fp16*ZSCL + norms ---
__global__ __launch_bounds__(256, 2)
void encode_k(const float* __restrict__ X, int n, const int* __restrict__ destMap,
              const float* __restrict__ W, const float* __restrict__ bias,
              __half* __restrict__ outH, float* __restrict__ outN) {
    extern __shared__ char smc[];
    float* sm = (float*)smc;
    float* ws = sm;                       // [128][132]
    float* xs = sm + 128 * 132;           // [32][132]
    int*   dests = (int*)(sm + 128 * 132 + 32 * 132);

    int tid = threadIdx.x;
    int base = blockIdx.x * 32;

    for (int t = tid; t < 128 * 32; t += 256) {
        int row = t >> 5, q = t & 31;
        float4 v = ((const float4*)W)[row * 32 + q];
        *(float4*)&ws[row * 132 + q * 4] = v;
    }
    for (int t = tid; t < 32 * 32; t += 256) {
        int row = t >> 5, q = t & 31;
        float4 v = make_float4(0.f, 0.f, 0.f, 0.f);
        if (base + row < n) v = ((const float4*)X)[(size_t)(base + row) * 32 + q];
        *(float4*)&xs[row * 132 + q * 4] = v;
    }
    if (tid < 32)
        dests[tid] = (base + tid < n) ? (destMap ? destMap[base + tid] : base + tid) : -1;
    __syncthreads();

    int cgrp = tid & 31, rgrp = tid >> 5;
    float acc[4][4];
#pragma unroll
    for (int i = 0; i < 4; ++i)
#pragma unroll
        for (int j = 0; j < 4; ++j) acc[i][j] = 0.f;

#pragma unroll 4
    for (int k = 0; k < 128; k += 4) {
        float4 a[4], w4[4];
#pragma unroll
        for (int i = 0; i < 4; ++i) a[i] = *(const float4*)&xs[(rgrp * 4 + i) * 132 + k];
#pragma unroll
        for (int j = 0; j < 4; ++j) w4[j] = *(const float4*)&ws[(cgrp + 32 * j) * 132 + k];
#pragma unroll
        for (int i = 0; i < 4; ++i)
#pragma unroll
            for (int j = 0; j < 4; ++j) {
                acc[i][j] = fmaf(a[i].x, w4[j].x, acc[i][j]);
                acc[i][j] = fmaf(a[i].y, w4[j].y, acc[i][j]);
                acc[i][j] = fmaf(a[i].z, w4[j].z, acc[i][j]);
                acc[i][j] = fmaf(a[i].w, w4[j].w, acc[i][j]);
            }
    }

    float nrm[4] = {0.f, 0.f, 0.f, 0.f};
#pragma unroll
    for (int j = 0; j < 4; ++j) {
        int dim = cgrp + 32 * j;
        float bb = bias[dim];
#pragma unroll
        for (int i = 0; i < 4; ++i) {
            float v = acc[i][j] + bb;
            acc[i][j] = v;
            nrm[i] = fmaf(v, v, nrm[i]);
        }
    }
#pragma unroll
    for (int i = 0; i < 4; ++i) {
        int d = dests[rgrp * 4 + i];
        if (d >= 0) {
#pragma unroll
            for (int j = 0; j < 4; ++j)
                outH[(size_t)d * 128 + cgrp + 32 * j] = __float2half_rn(acc[i][j] * ZSCL);
        }
        float s = nrm[i];
#pragma unroll
        for (int off = 16; off > 0; off >>= 1) s += __shfl_xor_sync(FULLMASK, s, off);
        if (cgrp == 0 && d >= 0) outN[d] = s * NSCL;
    }
}

// ---------------- main: single-term fp16 HMMA dist + per-class numerators ----
#define SM_ZH    0
#define SM_B     32768     // 2 stages x 32768
#define SM_CN    98304     // 2 x 512
#define SM_SACC  99328     // 128*10 floats
#define SM_TOTAL 104448

__device__ __forceinline__ void issue_tile(uint32_t sbase, const uint4* __restrict__ g,
                                           int tid) {
#pragma unroll
    for (int t = 0; t < 8; ++t) {
        int idx = tid + t * 256;            // 0..2047, = row*16 + chunk
        int row = idx >> 4, c = idx & 15;
        uint32_t saddr = sbase + row * 256 + ((c ^ (row & 7)) << 4);
        CP16(saddr, g + idx);
    }
}

__global__ __launch_bounds__(256, 2)
void nca_mma_k(const __half* __restrict__ zh_g, const float* __restrict__ zn2,
               const __half* __restrict__ ch_g, const float* __restrict__ cn_g,
               const int* __restrict__ classStart,
               float* __restrict__ part, int M, int N) {
    extern __shared__ char smc[];
    char* sm = smc;
    const uint32_t sb = smem_u32(sm);
    const int tid = threadIdx.x;
    const int w = tid >> 5, lane = tid & 31;
    const int warpM = w & 1, warpN = w >> 1;   // 2 x 4 warp grid; 64 x 32 per warp
    const int q2 = (lane & 3) * 2;
    const int tile = blockIdx.x, split = blockIdx.y;
    const int chunksTotal = M >> 7;
    const int cpb = (chunksTotal + NSPLIT - 1) / NSPLIT;
    const int cLo = split * cpb;
    const int cHi = min(cLo + cpb, chunksTotal);
    const int nch = cHi - cLo;

    for (int i = tid; i < 128 * NCLS; i += 256) ((float*)(sm + SM_SACC))[i] = 0.f;

    int cs[NCLS + 1];
#pragma unroll
    for (int k = 0; k <= NCLS; ++k) cs[k] = classStart[k];

    float znr[4][2];
#pragma unroll
    for (int mi = 0; mi < 4; ++mi) {
        int r = tile * 128 + warpM * 64 + mi * 16 + (lane >> 2);
        znr[mi][0] = zn2[r];
        znr[mi][1] = zn2[r + 8];
    }

    // prologue
    issue_tile(sb + SM_ZH, (const uint4*)zh_g + (size_t)tile * 2048, tid);
    issue_tile(sb + SM_B, (const uint4*)ch_g + (size_t)cLo * 2048, tid);
    if (tid < 32) CP16(sb + SM_CN + tid * 16, (const float*)cn_g + (size_t)cLo * 128 + tid * 4);
    CP_COMMIT();
    if (nch > 1) {
        issue_tile(sb + SM_B + 32768, (const uint4*)ch_g + (size_t)(cLo + 1) * 2048, tid);
        if (tid < 32) CP16(sb + SM_CN + 512 + tid * 16,
                           (const float*)cn_g + (size_t)(cLo + 1) * 128 + tid * 4);
    }
    CP_COMMIT();

    // ldmatrix address precompute
    uint32_t aoff[4], asw[4];
#pragma unroll
    for (int mi = 0; mi < 4; ++mi) {
        int row = warpM * 64 + mi * 16 + (lane & 15);
        aoff[mi] = row * 256;
        asw[mi] = row & 7;
    }
    const uint32_t achb = lane >> 4;
    uint32_t boff[2], bsw[2];
#pragma unroll
    for (int g = 0; g < 2; ++g) {
        int row = warpN * 32 + g * 16 + (lane & 7) + ((lane >> 4) << 3);
        boff[g] = row * 256;
        bsw[g] = row & 7;
    }
    const uint32_t bchb = (lane >> 3) & 1;

    for (int i = 0; i < nch; ++i) {
        CP_WAIT(1);
        __syncthreads();                     // stage (i&1) data visible to all

        const int cb = i & 1;
        const uint32_t bbase = sb + SM_B + cb * 32768;
        const uint32_t abase = sb + SM_ZH;

        float acc[4][4][4];
#pragma unroll
        for (int mi = 0; mi < 4; ++mi)
#pragma unroll
            for (int ni = 0; ni < 4; ++ni)
#pragma unroll
                for (int k = 0; k < 4; ++k) acc[mi][ni][k] = 0.f;

#pragma unroll
        for (int k8 = 0; k8 < 8; ++k8) {
            uint32_t af[4][4], bf[2][4];
            uint32_t ca = 2 * k8 + achb, cbk = 2 * k8 + bchb;
#pragma unroll
            for (int mi = 0; mi < 4; ++mi)
                LDSM4(af[mi], abase + aoff[mi] + ((ca ^ asw[mi]) << 4));
#pragma unroll
            for (int g = 0; g < 2; ++g)
                LDSM4(bf[g], bbase + boff[g] + ((cbk ^ bsw[g]) << 4));
#pragma unroll
            for (int mi = 0; mi < 4; ++mi)
#pragma unroll
                for (int ni = 0; ni < 4; ++ni) {
                    int g = ni >> 1, p = (ni & 1) * 2;
                    MMA_F16(acc[mi][ni], af[mi], bf[g][p], bf[g][p + 1]);
                }
        }

        // pull candidate norms into registers BEFORE freeing the stage
        float cnv[4][2];
#pragma unroll
        for (int ni = 0; ni < 4; ++ni) {
            cnv[ni][0] = *(const float*)(sm + SM_CN + cb * 512 + (warpN * 32 + ni * 8 + q2) * 4);
            cnv[ni][1] = *(const float*)(sm + SM_CN + cb * 512 + (warpN * 32 + ni * 8 + q2 + 1) * 4);
        }

        __syncthreads();                     // all reads of stage cb done

        // prefetch chunk i+2 into stage cb; DMA overlaps the epilogue below
        if (i + 2 < nch) {
            issue_tile(sb + SM_B + cb * 32768,
                       (const uint4*)ch_g + (size_t)(cLo + i + 2) * 2048, tid);
            if (tid < 32) CP16(sb + SM_CN + cb * 512 + tid * 16,
                               (const float*)cn_g + (size_t)(cLo + i + 2) * 128 + tid * 4);
        }
        CP_COMMIT();

        // dist -> exp(-dist): sq already scaled by log2(e)^2 via ZSCL/NSCL
#pragma unroll
        for (int ni = 0; ni < 4; ++ni)
#pragma unroll
            for (int mi = 0; mi < 4; ++mi)
#pragma unroll
                for (int k = 0; k < 4; ++k) {
                    float base = znr[mi][k >> 1] + cnv[ni][k & 1];
                    float sq = fmaf(-2.f, acc[mi][ni][k], base);
                    float dd;
                    asm("sqrt.approx.f32 %0, %1;" : "=f"(dd) : "f"(sq));
                    float nd = -dd;
                    asm("ex2.approx.f32 %0, %1;" : "=f"(acc[mi][ni][k]) : "f"(nd));
                }

        // class-segmented accumulation (candidates sorted by class)
        const int wb = (cLo + i) * 128 + warpN * 32;
        int c0 = 0;
        while (c0 < NCLS - 1 && cs[c0 + 1] <= wb) ++c0;
        int c1 = c0;
        while (c1 < NCLS - 1 && cs[c1 + 1] < wb + 32) ++c1;
        if (c0 == c1) {
            // fast path: whole 32-col slice in one class
#pragma unroll
            for (int mi = 0; mi < 4; ++mi)
#pragma unroll
                for (int h = 0; h < 2; ++h) {
                    float s = 0.f;
#pragma unroll
                    for (int ni = 0; ni < 4; ++ni)
#pragma unroll
                        for (int j = 0; j < 2; ++j) s += acc[mi][ni][h * 2 + j];
                    s += __shfl_xor_sync(FULLMASK, s, 1);
                    s += __shfl_xor_sync(FULLMASK, s, 2);
                    if ((lane & 3) == 0) {
                        int r = warpM * 64 + mi * 16 + (lane >> 2) + h * 8;
                        atomicAdd((float*)(sm + SM_SACC) + r * NCLS + c0, s);
                    }
                }
        } else {
            for (int c = c0; c <= c1; ++c) {
                int lo = max(cs[c] - wb, 0), hi = min(cs[c + 1] - wb, 32);
#pragma unroll
                for (int mi = 0; mi < 4; ++mi)
#pragma unroll
                    for (int h = 0; h < 2; ++h) {
                        float s = 0.f;
#pragma unroll
                        for (int ni = 0; ni < 4; ++ni)
#pragma unroll
                            for (int j = 0; j < 2; ++j) {
                                int nl = ni * 8 + q2 + j;
                                s += (nl >= lo && nl < hi) ? acc[mi][ni][h * 2 + j] : 0.f;
                            }
                        s += __shfl_xor_sync(FULLMASK, s, 1);
                        s += __shfl_xor_sync(FULLMASK, s, 2);
                        if ((lane & 3) == 0) {
                            int r = warpM * 64 + mi * 16 + (lane >> 2) + h * 8;
                            atomicAdd((float*)(sm + SM_SACC) + r * NCLS + c, s);
                        }
                    }
            }
        }
    }

    __syncthreads();
    if (tid < 128) {
        int qg = tile * 128 + tid;
#pragma unroll
        for (int c = 0; c < NCLS; ++c)
            part[((size_t)split * N + qg) * NCLS + c] =
                ((float*)(sm + SM_SACC))[tid * NCLS + c];
    }
}

// ---------------- finalize: combine splits, normalize, log ------------------
__global__ void finalize_k(const float* __restrict__ part, float* __restrict__ out, int N) {
    int n = blockIdx.x * blockDim.x + threadIdx.x;
    if (n >= N) return;
    float t[NCLS];
#pragma unroll
    for (int c = 0; c < NCLS; ++c) t[c] = 0.f;
    for (int s = 0; s < NSPLIT; ++s)
#pragma unroll
        for (int c = 0; c < NCLS; ++c) t[c] += part[((size_t)s * N + n) * NCLS + c];
    float tot = 0.f;
#pragma unroll
    for (int c = 0; c < NCLS; ++c) tot += t[c];
    float inv = 1.f / tot;
#pragma unroll
    for (int c = 0; c < NCLS; ++c) out[n * NCLS + c] = logf(fmaf(t[c], inv, 1e-7f));
}

// ---------------- launch ----------------------------------------------------
extern "C" void kernel_launch(void* const* d_in, const int* in_sizes, int n_in,
                              void* d_out, int out_size) {
    const float* x  = (const float*)d_in[0];
    const float* cx = (const float*)d_in[1];
    const int*   cy = (const int*)d_in[2];
    const float* W  = (const float*)d_in[3];
    const float* b  = (const float*)d_in[4];
    int N = in_sizes[0] / 128;
    int M = in_sizes[2];
    float* out = (float*)d_out;

    void *p_ch, *p_cn, *p_zh, *p_zn2, *p_dest, *p_hist, *p_cs, *p_part;
    cudaGetSymbolAddress(&p_ch, g_zc_h);
    cudaGetSymbolAddress(&p_cn, g_cn);
    cudaGetSymbolAddress(&p_zh, g_z_h);
    cudaGetSymbolAddress(&p_zn2, g_zn2);
    cudaGetSymbolAddress(&p_dest, g_destMap);
    cudaGetSymbolAddress(&p_hist, g_hist);
    cudaGetSymbolAddress(&p_cs, g_classStart);
    cudaGetSymbolAddress(&p_part, g_part);

    int NB = (M + HB - 1) / HB;
    hist_k<<<NB, HB>>>(cy, M, (int*)p_hist);
    scan_k<<<1, 32>>>((int*)p_hist, NB, (int*)p_cs);
    scatter_k<<<NB, HB>>>(cy, M, (const int*)p_hist, (const int*)p_cs, (int*)p_dest);

    size_t smemEnc = (size_t)(128 * 132 + 32 * 132) * 4 + 32 * 4;
    cudaFuncSetAttribute(encode_k, cudaFuncAttributeMaxDynamicSharedMemorySize, (int)smemEnc);
    encode_k<<<(N + 31) / 32, 256, smemEnc>>>(x, N, nullptr, W, b,
        (__half*)p_zh, (float*)p_zn2);
    encode_k<<<(M + 31) / 32, 256, smemEnc>>>(cx, M, (const int*)p_dest, W, b,
        (__half*)p_ch, (float*)p_cn);

    cudaFuncSetAttribute(nca_mma_k, cudaFuncAttributeMaxDynamicSharedMemorySize, SM_TOTAL);
    dim3 g(N / 128, NSPLIT);
    nca_mma_k<<<g, 256, SM_TOTAL>>>(
        (const __half*)p_zh, (const float*)p_zn2,
        (const __half*)p_ch, (const float*)p_cn,
        (const int*)p_cs, (float*)p_part, M, N);

    finalize_k<<<(N + 255) / 256, 256>>>((const float*)p_part, out, N);
}